// round 2
// baseline (speedup 1.0000x reference)
#include <cuda_runtime.h>
#include <cuda_bf16.h>

// Problem constants: x is [B, 3, 480, 640] fp32, B derived from out_size.
#define IMG_H 480
#define IMG_W 640
#define HW (IMG_H * IMG_W)          // 307200
#define CHW (3 * HW)
#define QPP (HW / 4)                // float4 quads per plane = 76800
#define RED_THREADS 256
#define RED_BLOCKS_PER_PLANE (QPP / RED_THREADS)  // 300, exact
#define MAX_B 64

// Per-batch accumulated gray sums (scratch; device global per harness rules).
__device__ float g_graysum[MAX_B];

__global__ void cr_zero_sums() {
    if (threadIdx.x < MAX_B) g_graysum[threadIdx.x] = 0.0f;
}

// Pass 1: per-batch sum of gray(clip(x * bf)) over the whole plane.
__global__ void __launch_bounds__(RED_THREADS)
cr_reduce_kernel(const float* __restrict__ x, const float* __restrict__ bf) {
    const int b = blockIdx.y;
    const int quad = blockIdx.x * RED_THREADS + threadIdx.x;  // 0..QPP-1, exact fit
    const float4* base = (const float4*)(x + (size_t)b * CHW);

    const float B = bf[b];
    float4 r4 = base[quad];
    float4 g4 = base[quad + QPP];
    float4 b4 = base[quad + 2 * QPP];

    float s = 0.0f;
    {
        float r, g, bl;
        #define ACC(comp) \
            r = __saturatef(r4.comp * B); \
            g = __saturatef(g4.comp * B); \
            bl = __saturatef(b4.comp * B); \
            s += 0.299f * r + 0.587f * g + 0.114f * bl;
        ACC(x) ACC(y) ACC(z) ACC(w)
        #undef ACC
    }

    __shared__ float sh[RED_THREADS];
    const int tid = threadIdx.x;
    sh[tid] = s;
    __syncthreads();
    #pragma unroll
    for (int o = RED_THREADS / 2; o > 0; o >>= 1) {
        if (tid < o) sh[tid] += sh[tid + o];
        __syncthreads();
    }
    if (tid == 0) atomicAdd(&g_graysum[b], sh[0]);
}

// Full per-pixel pipeline after the mean is known.
__device__ __forceinline__ void process_px(float& r, float& g, float& b,
                                           float B, float C, float S,
                                           float hfv, float m) {
    // brightness
    r = __saturatef(r * B);
    g = __saturatef(g * B);
    b = __saturatef(b * B);
    // contrast: blend with per-batch gray mean
    const float omC = 1.0f - C;
    r = __saturatef(C * r + omC * m);
    g = __saturatef(C * g + omC * m);
    b = __saturatef(C * b + omC * m);
    // saturation: blend with per-pixel gray
    const float gray = 0.299f * r + 0.587f * g + 0.114f * b;
    const float omS = 1.0f - S;
    r = __saturatef(S * r + omS * gray);
    g = __saturatef(S * g + omS * gray);
    b = __saturatef(S * b + omS * gray);
    // hue: RGB -> H(SV) -> rotate -> RGB, matching reference branch structure
    const float maxc = fmaxf(r, fmaxf(g, b));
    const float minc = fminf(r, fminf(g, b));
    const float v = maxc;
    const float cr = maxc - minc;
    const float crd = (cr == 0.0f) ? 1.0f : cr;
    const float s = cr / ((maxc == 0.0f) ? 1.0f : maxc);
    const float inv_crd = 1.0f / crd;
    const float rc = (maxc - r) * inv_crd;
    const float gc = (maxc - g) * inv_crd;
    const float bc = (maxc - b) * inv_crd;
    float h;
    if (maxc == r)      h = bc - gc;            // hr branch (priority)
    else if (maxc == g) h = 2.0f + rc - bc;     // hg branch
    else                h = 4.0f + gc - rc;     // hb branch
    h = h / 6.0f;
    h -= floorf(h);        // positive mod 1 (jnp semantics)
    h += hfv;
    h -= floorf(h);
    const float i6 = h * 6.0f;
    const float fi = floorf(i6);
    const float f = i6 - fi;
    int i = ((int)fi) % 6;
    const float p = v * (1.0f - s);
    const float q = v * (1.0f - f * s);
    const float t = v * (1.0f - (1.0f - f) * s);
    switch (i) {
        case 0:  r = v; g = t; b = p; break;
        case 1:  r = q; g = v; b = p; break;
        case 2:  r = p; g = v; b = t; break;
        case 3:  r = p; g = q; b = v; break;
        case 4:  r = t; g = p; b = v; break;
        default: r = v; g = p; b = q; break;
    }
}

__global__ void __launch_bounds__(256)
cr_main_kernel(const float* __restrict__ x,
               const float* __restrict__ bf, const float* __restrict__ cf,
               const float* __restrict__ sf, const float* __restrict__ hf,
               float* __restrict__ out, int nb) {
    const int idx = blockIdx.x * blockDim.x + threadIdx.x;
    const int total = nb * QPP;
    if (idx >= total) return;
    const int b = idx / QPP;
    const int quad = idx - b * QPP;

    const float4* inb = (const float4*)(x + (size_t)b * CHW);
    float4* outb = (float4*)(out + (size_t)b * CHW);

    const float B = bf[b];
    const float C = cf[b];
    const float S = sf[b];
    const float Hf = hf[b];
    const float m = g_graysum[b] * (1.0f / (float)HW);

    float4 r4 = inb[quad];
    float4 g4 = inb[quad + QPP];
    float4 b4 = inb[quad + 2 * QPP];

    process_px(r4.x, g4.x, b4.x, B, C, S, Hf, m);
    process_px(r4.y, g4.y, b4.y, B, C, S, Hf, m);
    process_px(r4.z, g4.z, b4.z, B, C, S, Hf, m);
    process_px(r4.w, g4.w, b4.w, B, C, S, Hf, m);

    outb[quad]           = r4;
    outb[quad + QPP]     = g4;
    outb[quad + 2 * QPP] = b4;
}

extern "C" void kernel_launch(void* const* d_in, const int* in_sizes, int n_in,
                              void* d_out, int out_size) {
    const float* x  = (const float*)d_in[0];
    const float* bf = (const float*)d_in[1];
    const float* cf = (const float*)d_in[2];
    const float* sf = (const float*)d_in[3];
    const float* hf = (const float*)d_in[4];
    float* out = (float*)d_out;

    const int nb = out_size / CHW;  // num_samples is 1 by shape constraints

    cr_zero_sums<<<1, MAX_B>>>();

    dim3 rgrid(RED_BLOCKS_PER_PLANE, nb);
    cr_reduce_kernel<<<rgrid, RED_THREADS>>>(x, bf);

    const int total = nb * QPP;
    const int threads = 256;
    const int blocks = (total + threads - 1) / threads;
    cr_main_kernel<<<blocks, threads>>>(x, bf, cf, sf, hf, out, nb);
}

// round 3
// speedup vs baseline: 1.5113x; 1.5113x over previous
#include <cuda_runtime.h>
#include <cuda_bf16.h>

// Problem constants: x is [B, 3, 480, 640] fp32, B derived from out_size.
#define IMG_H 480
#define IMG_W 640
#define HW (IMG_H * IMG_W)          // 307200
#define CHW (3 * HW)
#define QPP (HW / 4)                // float4 quads per plane = 76800
#define RED_THREADS 256
#define BLOCKS_PER_PLANE (QPP / RED_THREADS)  // 300, exact
#define MAX_B 64

// Per-batch accumulated gray sums (scratch; device global per harness rules).
__device__ float g_graysum[MAX_B];

__global__ void cr_zero_sums() {
    if (threadIdx.x < MAX_B) g_graysum[threadIdx.x] = 0.0f;
}

// Pass 1: per-batch sum of gray(clip(x * bf)). Default cache policy so x
// becomes L2-resident for pass 2.
__global__ void __launch_bounds__(RED_THREADS)
cr_reduce_kernel(const float* __restrict__ x, const float* __restrict__ bf) {
    const int b = blockIdx.y;
    const int quad = blockIdx.x * RED_THREADS + threadIdx.x;  // exact fit
    const float4* base = (const float4*)(x + (size_t)b * CHW);

    const float B = bf[b];
    float4 r4 = base[quad];
    float4 g4 = base[quad + QPP];
    float4 b4 = base[quad + 2 * QPP];

    float s = 0.0f;
    {
        float r, g, bl;
        #define ACC(comp) \
            r = __saturatef(r4.comp * B); \
            g = __saturatef(g4.comp * B); \
            bl = __saturatef(b4.comp * B); \
            s += 0.299f * r + 0.587f * g + 0.114f * bl;
        ACC(x) ACC(y) ACC(z) ACC(w)
        #undef ACC
    }

    // warp reduce, then one smem slot per warp, then warp-0 reduce + atomic
    #pragma unroll
    for (int o = 16; o > 0; o >>= 1)
        s += __shfl_xor_sync(0xFFFFFFFFu, s, o);

    __shared__ float warp_s[RED_THREADS / 32];
    const int lane = threadIdx.x & 31;
    const int wid = threadIdx.x >> 5;
    if (lane == 0) warp_s[wid] = s;
    __syncthreads();
    if (wid == 0) {
        s = (lane < RED_THREADS / 32) ? warp_s[lane] : 0.0f;
        #pragma unroll
        for (int o = 4; o > 0; o >>= 1)
            s += __shfl_xor_sync(0xFFFFFFFFu, s, o);
        if (lane == 0) atomicAdd(&g_graysum[b], s);
    }
}

// Full per-pixel pipeline after the mean is known.
__device__ __forceinline__ void process_px(float& r, float& g, float& b,
                                           float B, float C, float S,
                                           float hfv, float m) {
    // brightness
    r = __saturatef(r * B);
    g = __saturatef(g * B);
    b = __saturatef(b * B);
    // contrast: blend with per-batch gray mean
    const float omC = 1.0f - C;
    r = __saturatef(C * r + omC * m);
    g = __saturatef(C * g + omC * m);
    b = __saturatef(C * b + omC * m);
    // saturation: blend with per-pixel gray
    const float gray = 0.299f * r + 0.587f * g + 0.114f * b;
    const float omS = 1.0f - S;
    r = __saturatef(S * r + omS * gray);
    g = __saturatef(S * g + omS * gray);
    b = __saturatef(S * b + omS * gray);
    // hue: RGB -> H(SV) -> rotate -> RGB, matching reference branch structure
    const float maxc = fmaxf(r, fmaxf(g, b));
    const float minc = fminf(r, fminf(g, b));
    const float v = maxc;
    const float cr = maxc - minc;
    const float crd = (cr == 0.0f) ? 1.0f : cr;
    const float s = cr / ((maxc == 0.0f) ? 1.0f : maxc);
    const float inv_crd = 1.0f / crd;
    const float rc = (maxc - r) * inv_crd;
    const float gc = (maxc - g) * inv_crd;
    const float bc = (maxc - b) * inv_crd;
    float h;
    if (maxc == r)      h = bc - gc;            // hr branch (priority)
    else if (maxc == g) h = 2.0f + rc - bc;     // hg branch
    else                h = 4.0f + gc - rc;     // hb branch
    h = h * (1.0f / 6.0f);
    h -= floorf(h);        // positive mod 1 (jnp semantics)
    h += hfv;
    h -= floorf(h);
    const float i6 = h * 6.0f;
    const float fi = floorf(i6);
    const float f = i6 - fi;
    int i = ((int)fi) % 6;
    const float p = v * (1.0f - s);
    const float q = v * (1.0f - f * s);
    const float t = v * (1.0f - (1.0f - f) * s);
    switch (i) {
        case 0:  r = v; g = t; b = p; break;
        case 1:  r = q; g = v; b = p; break;
        case 2:  r = p; g = v; b = t; break;
        case 3:  r = p; g = q; b = v; break;
        case 4:  r = t; g = p; b = v; break;
        default: r = v; g = p; b = q; break;
    }
}

// Pass 2: grid (BLOCKS_PER_PLANE, nb) — exact fit, no div, no bounds check.
// Loads via __ldcs (last touch of x), stores via __stcs (never re-read).
__global__ void __launch_bounds__(256)
cr_main_kernel(const float* __restrict__ x,
               const float* __restrict__ bf, const float* __restrict__ cf,
               const float* __restrict__ sf, const float* __restrict__ hf,
               float* __restrict__ out) {
    const int b = blockIdx.y;
    const int quad = blockIdx.x * 256 + threadIdx.x;

    const float4* inb = (const float4*)(x + (size_t)b * CHW);
    float4* outb = (float4*)(out + (size_t)b * CHW);

    const float B = bf[b];
    const float C = cf[b];
    const float S = sf[b];
    const float Hf = hf[b];
    const float m = g_graysum[b] * (1.0f / (float)HW);

    float4 r4 = __ldcs(&inb[quad]);
    float4 g4 = __ldcs(&inb[quad + QPP]);
    float4 b4 = __ldcs(&inb[quad + 2 * QPP]);

    process_px(r4.x, g4.x, b4.x, B, C, S, Hf, m);
    process_px(r4.y, g4.y, b4.y, B, C, S, Hf, m);
    process_px(r4.z, g4.z, b4.z, B, C, S, Hf, m);
    process_px(r4.w, g4.w, b4.w, B, C, S, Hf, m);

    __stcs(&outb[quad],           r4);
    __stcs(&outb[quad + QPP],     g4);
    __stcs(&outb[quad + 2 * QPP], b4);
}

extern "C" void kernel_launch(void* const* d_in, const int* in_sizes, int n_in,
                              void* d_out, int out_size) {
    const float* x  = (const float*)d_in[0];
    const float* bf = (const float*)d_in[1];
    const float* cf = (const float*)d_in[2];
    const float* sf = (const float*)d_in[3];
    const float* hf = (const float*)d_in[4];
    float* out = (float*)d_out;

    const int nb = out_size / CHW;  // num_samples is 1 by shape constraints

    cr_zero_sums<<<1, MAX_B>>>();

    dim3 grid(BLOCKS_PER_PLANE, nb);
    cr_reduce_kernel<<<grid, RED_THREADS>>>(x, bf);
    cr_main_kernel<<<grid, 256>>>(x, bf, cf, sf, hf, out);
}